// round 14
// baseline (speedup 1.0000x reference)
#include <cuda_runtime.h>
#include <cuda_fp16.h>
#include <cstdint>

// ---------------- problem constants ----------------
#define N_NODES 8192
#define F_IN    256
#define D_OUT   64
#define LOG2E   1.4426950408889634f

// ---------------- device scratch (no allocation allowed) ----------------
__device__ float g_h[N_NODES * D_OUT];
__device__ float g_e1[N_NODES];
__device__ float g_e2[N_NODES];
// H in mma.m16n8k16 B-fragment order: [jb = j/16][n8b = d/8][lane]
__device__ uint2 g_hf[(N_NODES / 16) * 8 * 32];
__device__ float g_po[2 * N_NODES * D_OUT];   // partial O per j-half
__device__ float g_pz[2 * N_NODES];           // partial Z per j-half

// ---------------- helpers ----------------
__device__ __forceinline__ uint32_t smem_u32(const void* p) {
    uint32_t a;
    asm("{ .reg .u64 t; cvta.to.shared.u64 t, %1; cvt.u32.u64 %0, t; }"
        : "=r"(a) : "l"(p));
    return a;
}
__device__ __forceinline__ uint32_t pack_f16x2(float lo, float hi) {
    uint32_t r;
    asm("cvt.rn.f16x2.f32 %0, %1, %2;" : "=r"(r) : "f"(hi), "f"(lo));
    return r;
}
__device__ __forceinline__ float ex2(float x) {
    float r;
    asm("ex2.approx.ftz.f32 %0, %1;" : "=f"(r) : "f"(x));
    return r;
}
__device__ __forceinline__ unsigned long long pk2(float lo, float hi) {
    unsigned long long r;
    asm("mov.b64 %0, {%1, %2};" : "=l"(r) : "f"(lo), "f"(hi));
    return r;
}
__device__ __forceinline__ void upk2(float& lo, float& hi, unsigned long long v) {
    asm("mov.b64 {%0, %1}, %2;" : "=f"(lo), "=f"(hi) : "l"(v));
}
__device__ __forceinline__ void add2(unsigned long long& d, unsigned long long a) {
    asm("add.rn.f32x2 %0, %0, %1;" : "+l"(d) : "l"(a));
}
__device__ __forceinline__ void ldsm_x4(uint32_t (&r)[4], uint32_t addr) {
    asm volatile("ldmatrix.sync.aligned.m8n8.x4.shared.b16 {%0,%1,%2,%3}, [%4];"
                 : "=r"(r[0]), "=r"(r[1]), "=r"(r[2]), "=r"(r[3]) : "r"(addr));
}
__device__ __forceinline__ void mma16816(float (&c)[4], const uint32_t (&a)[4],
                                         const uint32_t* b) {
    asm volatile("mma.sync.aligned.m16n8k16.row.col.f32.f16.f16.f32 "
        "{%0,%1,%2,%3}, {%4,%5,%6,%7}, {%8,%9}, {%0,%1,%2,%3};"
        : "+f"(c[0]), "+f"(c[1]), "+f"(c[2]), "+f"(c[3])
        : "r"(a[0]), "r"(a[1]), "r"(a[2]), "r"(a[3]), "r"(b[0]), "r"(b[1]));
}

// ---------------- kernel 1: h = x @ trans, fragment output + fused e1/e2 ----------------
__global__ void k_h_gemm(const float* __restrict__ x,
                         const float* __restrict__ trans,
                         const float* __restrict__ attn) {
    __shared__ float xs[16 * F_IN];
    __shared__ float ts[64 * D_OUT];
    __shared__ float trs[64 * 17];

    const int t = threadIdx.x;
    const int d = t & 63;
    const int rg = t >> 6;
    const int ibase = blockIdx.x * 16;

    {
        const float4* xg4 = reinterpret_cast<const float4*>(x) + (size_t)ibase * (F_IN / 4);
        float4* xs4 = reinterpret_cast<float4*>(xs);
        #pragma unroll
        for (int q = 0; q < 4; q++) xs4[t + q * 256] = xg4[t + q * 256];
    }

    float acc[4] = {0.f, 0.f, 0.f, 0.f};

    for (int kc = 0; kc < 4; kc++) {
        {
            const float4* tg4 = reinterpret_cast<const float4*>(trans) + kc * 1024;
            float4* ts4 = reinterpret_cast<float4*>(ts);
            #pragma unroll
            for (int q = 0; q < 4; q++) ts4[t + q * 256] = tg4[t + q * 256];
        }
        __syncthreads();
        #pragma unroll 4
        for (int k4 = 0; k4 < 16; k4++) {
            float4 xv[4];
            #pragma unroll
            for (int r = 0; r < 4; r++)
                xv[r] = *reinterpret_cast<const float4*>(
                    &xs[(rg * 4 + r) * F_IN + kc * 64 + k4 * 4]);
            #pragma unroll
            for (int kk = 0; kk < 4; kk++) {
                const float tv = ts[(k4 * 4 + kk) * 64 + d];
                #pragma unroll
                for (int r = 0; r < 4; r++)
                    acc[r] = fmaf(reinterpret_cast<const float*>(&xv[r])[kk],
                                  tv, acc[r]);
            }
        }
        __syncthreads();
    }

    #pragma unroll
    for (int r = 0; r < 4; r++) {
        g_h[(size_t)(ibase + rg * 4 + r) * D_OUT + d] = acc[r];
        trs[d * 17 + rg * 4 + r] = acc[r];
    }
    __syncthreads();

    // B fragments for jb = blockIdx.x
    {
        const int l = t & 31;
        const int n8b = t >> 5;
        const int n = n8b * 8 + (l >> 2);
        const int k0 = (l & 3) * 2;
        const float* r = trs + n * 17;
        uint2 v;
        v.x = pack_f16x2(r[k0], r[k0 + 1]);
        v.y = pack_f16x2(r[k0 + 8], r[k0 + 9]);
        g_hf[((size_t)blockIdx.x * 8 + n8b) * 32 + l] = v;
    }

    // fused e1/e2: 32 threads, one (row, half) each
    if (t < 32) {
        const int r = t & 15;
        const int sel = t >> 4;
        const float* ap = attn + sel * 64;
        float s = 0.f;
        #pragma unroll 8
        for (int dd = 0; dd < 64; dd++)
            s = fmaf(trs[dd * 17 + r], __ldg(ap + dd), s);
        (sel ? g_e2 : g_e1)[ibase + r] = s;
    }
}

// ---------------- kernel 2: warp-specialized attention, j-split halves ----------------
// CTA: 32 rows x 4096 j (one half). Tile: 32 x 64. 64 tiles. Grid 512, 2/SM.
#define ROWS 32
#define PROW 144
#define PHI0 0
#define PHI1 4608
#define SMEM_BYTES (9216 + 128)

#define NTILES 64

__global__ __launch_bounds__(512, 2)
void k_attn_ws(const int* __restrict__ mask,
               const float* __restrict__ e2g) {
    extern __shared__ char dsmem[];

    const int t = threadIdx.x;
    const int lane = t & 31;
    const int w = t >> 5;
    const int ib = blockIdx.x & 255;
    const int half = blockIdx.x >> 8;
    const int ibase = ib * ROWS;
    const int jbase = half * 4096;

    const uint32_t sbase = smem_u32(dsmem);
    const uint32_t abase = (sbase + 127) & ~127u;
    char* ab = dsmem + (abase - sbase);

    // ============ producer state (warps 0-7, t < 256) ============
    const int prow = t >> 3;            // row within block (0..31)
    const int j0 = (t & 7) << 3;        // 8 j per thread
    const float ei8 = g_e1[ibase + prow] * LOG2E - 8.0f;

    const uint4* mrow_p = reinterpret_cast<const uint4*>(
        mask + (size_t)(ibase + prow) * N_NODES + jbase + j0);  // tile: 16 uint4

    uint4 mreg[2];
    unsigned long long zacc = 0ull;

    // ============ consumer state (warps 8-15) ============
    const int wc = w - 8;
    const int mgrp = wc & 1;            // m-group (16 rows)
    const int ngrp = wc >> 1;           // n-group (16 cols = 2 n8 frags)
    const uint32_t a_base = (uint32_t)(
        (mgrp * 16 + (lane & 15)) * PROW + ((lane >> 4) << 4));
    // B fragments: jb = half*256 + it*4 + kk
    const uint2* bgp = g_hf + (size_t)half * 65536
                            + (size_t)(ngrp * 2) * 32 + lane;

    uint2 bf[8];
    float acc[2][4];
    #pragma unroll
    for (int nf = 0; nf < 2; nf++)
        #pragma unroll
        for (int c = 0; c < 4; c++) acc[nf][c] = 0.f;

    // prologue
    if (w < 8) {
        mreg[0] = mrow_p[0];
        mreg[1] = mrow_p[1];
    } else {
        #pragma unroll
        for (int kk = 0; kk < 4; kk++) {
            const uint2* bp = bgp + (size_t)kk * 256;
            bf[kk * 2]     = __ldg(bp);
            bf[kk * 2 + 1] = __ldg(bp + 32);
        }
    }

    for (int it = 0; it <= NTILES; it++) {
        __syncthreads();
        if (w < 8) {
            if (it < NTILES) {
                const uint32_t phioff = (it & 1) ? PHI1 : PHI0;
                const float4* e2p = reinterpret_cast<const float4*>(
                    e2g + jbase + it * 64 + j0);
                uint32_t hiu[4];
                #pragma unroll
                for (int g = 0; g < 2; g++) {
                    const float4 ev = __ldg(e2p + g);
                    const uint4 mm = mreg[g];
                    const float e4[4] = {ev.x, ev.y, ev.z, ev.w};
                    const uint32_t m4[4] = {mm.x, mm.y, mm.z, mm.w};
                    float p[4];
                    #pragma unroll
                    for (int k = 0; k < 4; k++) {
                        const float a = fmaf(e4[k], LOG2E, ei8);
                        const float b = fmaf(a, 0.2f, -6.4f);
                        const float pe = ex2(fmaxf(a, b));
                        p[k] = __uint_as_float(m4[k] * __float_as_uint(pe));
                    }
                    add2(zacc, pk2(p[0], p[1]));
                    add2(zacc, pk2(p[2], p[3]));
                    hiu[g * 2]     = pack_f16x2(p[0], p[1]);
                    hiu[g * 2 + 1] = pack_f16x2(p[2], p[3]);
                }
                *reinterpret_cast<uint4*>(ab + phioff + prow * PROW + j0 * 2) =
                    make_uint4(hiu[0], hiu[1], hiu[2], hiu[3]);
                {
                    const int nt = (it + 1 < NTILES) ? it + 1 : 0;
                    const uint4* mp = mrow_p + nt * 16;
                    mreg[0] = mp[0];
                    mreg[1] = mp[1];
                }
            }
        } else {
            if (it >= 1) {
                const uint32_t phi = abase + (((it - 1) & 1) ? PHI1 : PHI0);
                #pragma unroll
                for (int kk = 0; kk < 4; kk++) {
                    uint32_t ah[4];
                    ldsm_x4(ah, phi + a_base + kk * 32);
                    mma16816(acc[0], ah, &bf[kk * 2].x);
                    mma16816(acc[1], ah, &bf[kk * 2 + 1].x);
                }
                {
                    const int nt = (it < NTILES) ? it : 0;
                    const uint2* bp0 = bgp + (size_t)nt * 1024;
                    #pragma unroll
                    for (int kk = 0; kk < 4; kk++) {
                        const uint2* bp = bp0 + (size_t)kk * 256;
                        bf[kk * 2]     = __ldg(bp);
                        bf[kk * 2 + 1] = __ldg(bp + 32);
                    }
                }
            }
        }
    }

    // ---- epilogue (no barrier needed: partials go to global) ----
    if (w < 8) {
        float zlo, zhi;
        upk2(zlo, zhi, zacc);
        float zsum = zlo + zhi;
        zsum += __shfl_xor_sync(0xffffffffu, zsum, 1);
        zsum += __shfl_xor_sync(0xffffffffu, zsum, 2);
        zsum += __shfl_xor_sync(0xffffffffu, zsum, 4);
        if ((t & 7) == 0) g_pz[half * N_NODES + ibase + prow] = zsum;
    } else {
        float* po = g_po + (size_t)half * (N_NODES * D_OUT);
        const int r0 = mgrp * 16 + (lane >> 2);
        #pragma unroll
        for (int nf = 0; nf < 2; nf++) {
            const int col = ngrp * 16 + nf * 8 + (lane & 3) * 2;
            *reinterpret_cast<float2*>(
                po + (size_t)(ibase + r0) * D_OUT + col) =
                make_float2(acc[nf][0], acc[nf][1]);
            *reinterpret_cast<float2*>(
                po + (size_t)(ibase + r0 + 8) * D_OUT + col) =
                make_float2(acc[nf][2], acc[nf][3]);
        }
    }
}

// ---------------- kernel 3: combine the two j-halves ----------------
__global__ void k_combine(float* __restrict__ out) {
    const int idx = blockIdx.x * 256 + threadIdx.x;   // 8192*16 float4s
    const int i = idx >> 4;
    const float4 a = reinterpret_cast<const float4*>(g_po)[idx];
    const float4 b = reinterpret_cast<const float4*>(g_po)[idx + (N_NODES * D_OUT / 4)];
    const float rz = 1.0f / (g_pz[i] + g_pz[N_NODES + i]);
    float4 o;
    o.x = (a.x + b.x) * rz;
    o.y = (a.y + b.y) * rz;
    o.z = (a.z + b.z) * rz;
    o.w = (a.w + b.w) * rz;
    reinterpret_cast<float4*>(out)[idx] = o;
}

// ---------------- launch ----------------
extern "C" void kernel_launch(void* const* d_in, const int* in_sizes, int n_in,
                              void* d_out, int out_size) {
    const float* x     = (const float*)d_in[0];   // [8192, 256]
    const int*   mask  = (const int*)d_in[1];     // [8192, 8192]
    const float* trans = (const float*)d_in[2];   // [256, 64]
    const float* attn  = (const float*)d_in[3];   // [128, 1]
    float* out = (float*)d_out;                   // [8192, 64]

    cudaFuncSetAttribute(k_attn_ws, cudaFuncAttributeMaxDynamicSharedMemorySize,
                         SMEM_BYTES);

    k_h_gemm<<<N_NODES / 16, 256>>>(x, trans, attn);

    float* e2g;
    cudaGetSymbolAddress((void**)&e2g, g_e2);
    k_attn_ws<<<512, 512, SMEM_BYTES>>>(mask, e2g);
    k_combine<<<(N_NODES * D_OUT / 4) / 256, 256>>>(out);
}